// round 10
// baseline (speedup 1.0000x reference)
#include <cuda_runtime.h>
#include <cuda_bf16.h>

// S4 Vandermonde kernel: out[h,l] = 2*Re( sum_n Ceff[h,n] * w[h,n]^l )
//   w = exp(dtA), Ceff = Bc*Cc*(w-1)/A ;  H=512, NH=32, L=8192.
//
// R9: R6 skeleton (grid=256, SPT-equivalent chunk 4096, single static main
// loop -- the codegen-safe shape) + DUAL-RESIDUE chains: each lane owns
// l = j (mod 64) and l = j+32 (mod 64), both stepping by w^64 with a SHARED
// (P,Q) coefficient set.  Same instructions per output as R6, but 32
// independent recurrence chains + 2 independent sum-trees per body fill the
// issue-stall windows that bounded R6 at ~163 cyc/warp-step.

#define HH 512
#define NHALF 32
#define LL 8192
#define WPB 4
#define CHUNK 4096                   // l-values per warp
#define NSTEP 64                     // steps of 64 l each

typedef unsigned long long u64;

__device__ __forceinline__ u64 pk2(float lo, float hi) {
    u64 r; asm("mov.b64 %0,{%1,%2};" : "=l"(r) : "f"(lo), "f"(hi)); return r;
}
__device__ __forceinline__ void upk2(u64 v, float& lo, float& hi) {
    asm("mov.b64 {%0,%1},%2;" : "=f"(lo), "=f"(hi) : "l"(v));
}
__device__ __forceinline__ u64 f2mul(u64 a, u64 b) {
    u64 r; asm("mul.rn.f32x2 %0,%1,%2;" : "=l"(r) : "l"(a), "l"(b)); return r;
}
__device__ __forceinline__ u64 f2fma(u64 a, u64 b, u64 c) {
    u64 r; asm("fma.rn.f32x2 %0,%1,%2,%3;" : "=l"(r) : "l"(a), "l"(b), "l"(c)); return r;
}
__device__ __forceinline__ u64 f2add(u64 a, u64 b) {
    u64 r; asm("add.rn.f32x2 %0,%1,%2;" : "=l"(r) : "l"(a), "l"(b)); return r;
}

__device__ __forceinline__ float2 cmulf(float2 a, float2 b) {
    return make_float2(fmaf(a.x, b.x, -a.y * b.y), fmaf(a.x, b.y, a.y * b.x));
}

// reduction tree over 16 packed pairs -> scalar (lo+hi)
__device__ __forceinline__ float sumtree16(const u64* R) {
    u64 s0 = f2add(R[0], R[8]);
    u64 s1 = f2add(R[1], R[9]);
    u64 s2 = f2add(R[2], R[10]);
    u64 s3 = f2add(R[3], R[11]);
    u64 s4 = f2add(R[4], R[12]);
    u64 s5 = f2add(R[5], R[13]);
    u64 s6 = f2add(R[6], R[14]);
    u64 s7 = f2add(R[7], R[15]);
    s0 = f2add(s0, s4); s1 = f2add(s1, s5);
    s2 = f2add(s2, s6); s3 = f2add(s3, s7);
    s0 = f2add(s0, s2); s1 = f2add(s1, s3);
    s0 = f2add(s0, s1);
    float lo, hi; upk2(s0, lo, hi);
    return lo + hi;
}

#define PI2_HI 6.2831854820251465f
#define PI2_LO (-1.7484561e-7f)
#define INV2PI 0.15915494309189535f

// accurate sin/cos with two-float 2*pi reduction
__device__ __forceinline__ void redsc(float th, float* s, float* c) {
    float kk = rintf(th * INV2PI);
    float r  = fmaf(-kk, PI2_HI, th);
    r        = fmaf(-kk, PI2_LO, r);
    __sincosf(r, s, c);
}

__global__ void __launch_bounds__(128, 2)
s4_vandermonde_kernel(const float* __restrict__ log_dt,
                      const float* __restrict__ log_A_real,
                      const float* __restrict__ A_imag,
                      const float* __restrict__ Bmat,
                      const float* __restrict__ Cmat,
                      float* __restrict__ out)
{
    // per warp, per mode: row0={p64,q64,wm64r,wm64i} row1={c2r,c2i,dre,dim}
    //                     row2={w32r,w32i,-,-}
    __shared__ float4 mp[WPB][NHALF][3];

    const int w   = threadIdx.x >> 5;
    const int j   = threadIdx.x & 31;
    const int gw  = blockIdx.x * WPB + w;
    const int h   = gw >> 1;
    const int chk = gw & 1;

    // ---------- phase A: lane j computes mode j params ----------
    {
        const int n = j;
        const float dt  = __expf(log_dt[h]);
        const float ar  = -__expf(log_A_real[h * NHALF + n]);
        const float aiv = -A_imag[h * NHALF + n];
        const float dre = dt * ar;
        const float dim = dt * aiv;

        // w^64 -> p, q ; w^-64 (clamped)
        float s64, c64; redsc(64.f * dim, &s64, &c64);
        float mg64 = __expf(64.f * dre);
        float p = 2.0f * mg64 * c64;
        float q = -mg64 * mg64;
        float mgm = __expf(fminf(-64.f * dre, 60.f));
        float wmr = mgm * c64, wmi = -mgm * s64;
        // w^32 (seed for second residue)
        float s32, c32; redsc(32.f * dim, &s32, &c32);
        float mg32 = __expf(32.f * dre);
        // 2*Ceff = 2*Bc*Cc*(w^1 - 1)/A
        float s1v, c1v; redsc(dim, &s1v, &c1v);
        float mg1 = __expf(dre);
        float2 w1  = make_float2(mg1 * c1v, mg1 * s1v);
        float2 num = make_float2(w1.x - 1.0f, w1.y);
        float  inv = 2.0f / fmaf(ar, ar, aiv * aiv);
        float2 ia  = make_float2(ar * inv, -aiv * inv);
        const float2* Bv = (const float2*)Bmat;
        const float2* Cv = (const float2*)Cmat;
        float2 bc  = cmulf(Bv[h * NHALF + n], Cv[h * NHALF + n]);
        float2 c2  = cmulf(cmulf(bc, num), ia);

        mp[w][n][0] = make_float4(p, q, wmr, wmi);
        mp[w][n][1] = make_float4(c2.x, c2.y, dre, dim);
        mp[w][n][2] = make_float4(mg32 * c32, mg32 * s32, 0.f, 0.f);
    }
    __syncwarp();

    // ---------- phase B: seeds for both residues at l0 = chk*4096 + j ----------
    const float l0f = (float)(chk * CHUNK + j);
    u64 U0[NHALF / 2], V0[NHALF / 2], U1[NHALF / 2], V1[NHALF / 2];
    u64 P[NHALF / 2], Q[NHALF / 2];
    #pragma unroll
    for (int m = 0; m < NHALF / 2; m++) {
        float v0[2], u0[2], v1[2], u1[2], pp[2], qq[2];
        #pragma unroll
        for (int e = 0; e < 2; e++) {
            const int n = 2 * m + e;
            float4 a = mp[w][n][0];
            float4 b = mp[w][n][1];
            float4 c = mp[w][n][2];
            pp[e] = a.x; qq[e] = a.y;
            float sn, cs;
            redsc(b.w * l0f, &sn, &cs);           // theta = dim*l0
            float mg  = __expf(b.z * l0f);        // dre*l0 <= 0 -> mg <= 1
            float zr  = mg * cs, zi = mg * sn;
            float z0r = fmaf(b.x, zr, -b.y * zi); // z0 = 2Ceff * w^l0
            float z0i = fmaf(b.x, zi,  b.y * zr);
            v0[e] = z0r;                          // r(l0)
            u0[e] = fmaf(z0r, a.z, -z0i * a.w);   // Re(z0 * w^-64)
            float z1r = fmaf(z0r, c.x, -z0i * c.y);   // z1 = z0 * w^32
            float z1i = fmaf(z0r, c.y,  z0i * c.x);
            v1[e] = z1r;                          // r(l0+32)
            u1[e] = fmaf(z1r, a.z, -z1i * a.w);   // Re(z1 * w^-64)
        }
        V0[m] = pk2(v0[0], v0[1]);
        U0[m] = pk2(u0[0], u0[1]);
        V1[m] = pk2(v1[0], v1[1]);
        U1[m] = pk2(u1[0], u1[1]);
        P[m]  = pk2(pp[0], pp[1]);
        Q[m]  = pk2(qq[0], qq[1]);
    }

    // ---------- main loop: invariant V = r_i, U = r_{i-1} (per residue) ----------
    float* opp = out + h * LL + chk * CHUNK + j;
    #pragma unroll 1
    for (int i = 0; i < NSTEP; i += 2) {
        opp[i * 64]      = sumtree16(V0);         // res0: l = l0 + 64*i
        opp[i * 64 + 32] = sumtree16(V1);         // res1: l = l0 + 64*i + 32
        #pragma unroll
        for (int m = 0; m < NHALF / 2; m++)       // U <- r_{i+1}
            U0[m] = f2fma(P[m], V0[m], f2mul(Q[m], U0[m]));
        #pragma unroll
        for (int m = 0; m < NHALF / 2; m++)
            U1[m] = f2fma(P[m], V1[m], f2mul(Q[m], U1[m]));
        opp[(i + 1) * 64]      = sumtree16(U0);   // r_{i+1}
        opp[(i + 1) * 64 + 32] = sumtree16(U1);
        #pragma unroll
        for (int m = 0; m < NHALF / 2; m++)       // V <- r_{i+2}
            V0[m] = f2fma(P[m], U0[m], f2mul(Q[m], V0[m]));
        #pragma unroll
        for (int m = 0; m < NHALF / 2; m++)
            V1[m] = f2fma(P[m], U1[m], f2mul(Q[m], V1[m]));
    }
}

extern "C" void kernel_launch(void* const* d_in, const int* in_sizes, int n_in,
                              void* d_out, int out_size)
{
    const float* log_dt     = (const float*)d_in[0];
    const float* log_A_real = (const float*)d_in[1];
    const float* A_imag     = (const float*)d_in[2];
    const float* Bmat       = (const float*)d_in[3];
    const float* Cmat       = (const float*)d_in[4];
    float* out = (float*)d_out;

    dim3 grid(HH * 2 / WPB);   // 256 blocks
    dim3 block(32 * WPB);      // 128 threads
    s4_vandermonde_kernel<<<grid, block>>>(log_dt, log_A_real, A_imag,
                                           Bmat, Cmat, out);
}

// round 11
// speedup vs baseline: 1.4305x; 1.4305x over previous
#include <cuda_runtime.h>
#include <cuda_bf16.h>

// S4 Vandermonde kernel: out[h,l] = 2*Re( sum_n Ceff[h,n] * w[h,n]^l )
//   w = exp(dtA), Ceff = Bc*Cc*(w-1)/A ;  H=512, NH=32, L=8192.
//
// R10 = R6 skeleton EXACTLY (grid=256, block=128, one fixed (h,chk) per warp,
// static SPT=128 main loop, unroll 4, Goertzel r_{i+1} = p r_i + q r_{i-1})
// with ONE change: the start state is seeded by direct per-mode exp/sincos
// (MUFU pipe, proven in R7/R8) instead of binary powering from a w^(2^k)
// table (~256 complex muls/lane on the fma pipe).  Setup leaves the fma
// critical path; main loop untouched.

#define HH 512
#define NHALF 32
#define LL 8192
#define SPT 128                      // recurrence steps per lane
#define WPB 4                        // warps per block
#define CHUNK (32 * SPT)             // 4096 l-values per warp
#define CHUNKS_PER_H (LL / CHUNK)    // 2

typedef unsigned long long u64;

__device__ __forceinline__ u64 pk2(float lo, float hi) {
    u64 r; asm("mov.b64 %0,{%1,%2};" : "=l"(r) : "f"(lo), "f"(hi)); return r;
}
__device__ __forceinline__ void upk2(u64 v, float& lo, float& hi) {
    asm("mov.b64 {%0,%1},%2;" : "=f"(lo), "=f"(hi) : "l"(v));
}
__device__ __forceinline__ u64 f2mul(u64 a, u64 b) {
    u64 r; asm("mul.rn.f32x2 %0,%1,%2;" : "=l"(r) : "l"(a), "l"(b)); return r;
}
__device__ __forceinline__ u64 f2fma(u64 a, u64 b, u64 c) {
    u64 r; asm("fma.rn.f32x2 %0,%1,%2,%3;" : "=l"(r) : "l"(a), "l"(b), "l"(c)); return r;
}
__device__ __forceinline__ u64 f2add(u64 a, u64 b) {
    u64 r; asm("add.rn.f32x2 %0,%1,%2;" : "=l"(r) : "l"(a), "l"(b)); return r;
}

__device__ __forceinline__ float2 cmulf(float2 a, float2 b) {
    return make_float2(fmaf(a.x, b.x, -a.y * b.y), fmaf(a.x, b.y, a.y * b.x));
}

// reduction tree over 16 packed pairs -> scalar (lo+hi)
__device__ __forceinline__ float sumtree16(const u64* R) {
    u64 s0 = f2add(R[0], R[8]);
    u64 s1 = f2add(R[1], R[9]);
    u64 s2 = f2add(R[2], R[10]);
    u64 s3 = f2add(R[3], R[11]);
    u64 s4 = f2add(R[4], R[12]);
    u64 s5 = f2add(R[5], R[13]);
    u64 s6 = f2add(R[6], R[14]);
    u64 s7 = f2add(R[7], R[15]);
    s0 = f2add(s0, s4); s1 = f2add(s1, s5);
    s2 = f2add(s2, s6); s3 = f2add(s3, s7);
    s0 = f2add(s0, s2); s1 = f2add(s1, s3);
    s0 = f2add(s0, s1);
    float lo, hi; upk2(s0, lo, hi);
    return lo + hi;
}

#define PI2_HI 6.2831854820251465f
#define PI2_LO (-1.7484561e-7f)
#define INV2PI 0.15915494309189535f

// accurate sin/cos with two-float 2*pi reduction
__device__ __forceinline__ void redsc(float th, float* s, float* c) {
    float kk = rintf(th * INV2PI);
    float r  = fmaf(-kk, PI2_HI, th);
    r        = fmaf(-kk, PI2_LO, r);
    __sincosf(r, s, c);
}

// per-mode start values from the smem param rows at offset l0f
__device__ __forceinline__ void start_mode(const float4* mpn, float l0f,
                                           float& r0, float& rm,
                                           float& p,  float& q) {
    float4 a = mpn[0];   // p, q, wm32r, wm32i
    float4 b = mpn[1];   // c2r, c2i, dre, dim
    p = a.x; q = a.y;
    float sn, cs;
    redsc(b.w * l0f, &sn, &cs);          // theta = dim*l0 (same rounding as ref)
    float mg  = __expf(b.z * l0f);       // dre*l0 <= 0 -> mg <= 1
    float zr  = mg * cs, zi = mg * sn;
    float z0r = fmaf(b.x, zr, -b.y * zi);
    float z0i = fmaf(b.x, zi,  b.y * zr);
    r0 = z0r;                            // r(l0)
    rm = fmaf(z0r, a.z, -z0i * a.w);     // Re(z0 * w^-32) = r(l0-32)
}

__global__ void __launch_bounds__(128, 2)
s4_vandermonde_kernel(const float* __restrict__ log_dt,
                      const float* __restrict__ log_A_real,
                      const float* __restrict__ A_imag,
                      const float* __restrict__ Bmat,
                      const float* __restrict__ Cmat,
                      float* __restrict__ out)
{
    // per warp, per mode: row0 = {p, q, wm32r, wm32i}, row1 = {c2r, c2i, dre, dim}
    __shared__ float4 mp[WPB][NHALF][2];

    const int w   = threadIdx.x >> 5;
    const int j   = threadIdx.x & 31;
    const int gw  = blockIdx.x * WPB + w;
    const int h   = gw >> 1;       // / CHUNKS_PER_H
    const int chk = gw & 1;

    // ---------- phase A: lane j computes mode j params (MUFU-heavy) ----------
    {
        const int n = j;
        const float dt  = __expf(log_dt[h]);
        const float ar  = -__expf(log_A_real[h * NHALF + n]);
        const float aiv = -A_imag[h * NHALF + n];
        const float dre = dt * ar;
        const float dim = dt * aiv;

        // w^32 -> p, q; w^-32 (magnitude clamped; when clamped q underflowed to 0)
        float s32, c32; redsc(32.f * dim, &s32, &c32);
        float mg32 = __expf(32.f * dre);
        float w32r = mg32 * c32, w32i = mg32 * s32;
        float p = w32r + w32r;
        float q = -fmaf(w32r, w32r, w32i * w32i);
        float mgm = __expf(fminf(-32.f * dre, 60.f));
        float wmr = mgm * c32, wmi = -mgm * s32;
        // 2*Ceff = 2*Bc*Cc*(w^1 - 1)/A
        float s1v, c1v; redsc(dim, &s1v, &c1v);
        float mg1 = __expf(dre);
        float2 w1  = make_float2(mg1 * c1v, mg1 * s1v);
        float2 num = make_float2(w1.x - 1.0f, w1.y);
        float  inv = 2.0f / fmaf(ar, ar, aiv * aiv);
        float2 ia  = make_float2(ar * inv, -aiv * inv);
        const float2* Bv = (const float2*)Bmat;
        const float2* Cv = (const float2*)Cmat;
        float2 bc  = cmulf(Bv[h * NHALF + n], Cv[h * NHALF + n]);
        float2 c2  = cmulf(cmulf(bc, num), ia);

        mp[w][n][0] = make_float4(p, q, wmr, wmi);
        mp[w][n][1] = make_float4(c2.x, c2.y, dre, dim);
    }
    __syncwarp();

    // ---------- phase B: direct seed at l0 = chk*4096 + j ----------
    const float l0f = (float)(chk * CHUNK + j);
    u64 RB[NHALF / 2], RA[NHALF / 2], P[NHALF / 2], Q[NHALF / 2];
    #pragma unroll
    for (int m = 0; m < NHALF / 2; m++) {
        float r0a, rma, pa, qa, r0b, rmb, pb, qb;
        start_mode(&mp[w][2 * m][0],     l0f, r0a, rma, pa, qa);
        start_mode(&mp[w][2 * m + 1][0], l0f, r0b, rmb, pb, qb);
        RB[m] = pk2(r0a, r0b);        // r_0
        RA[m] = pk2(rma, rmb);        // r_-1
        P[m]  = pk2(pa, pb);
        Q[m]  = pk2(qa, qb);
    }

    // ---------- main recurrence, unrolled by 2 with role swap (R6 body) ----------
    float* op = out + h * LL + chk * CHUNK + j;
    #pragma unroll 4
    for (int i = 0; i < SPT; i += 2) {
        op[i * 32] = sumtree16(RB);                   // r_i
        #pragma unroll
        for (int m = 0; m < NHALF / 2; m++)           // RA <- r_{i+1}
            RA[m] = f2fma(P[m], RB[m], f2mul(Q[m], RA[m]));
        op[(i + 1) * 32] = sumtree16(RA);             // r_{i+1}
        #pragma unroll
        for (int m = 0; m < NHALF / 2; m++)           // RB <- r_{i+2}
            RB[m] = f2fma(P[m], RA[m], f2mul(Q[m], RB[m]));
    }
}

extern "C" void kernel_launch(void* const* d_in, const int* in_sizes, int n_in,
                              void* d_out, int out_size)
{
    const float* log_dt     = (const float*)d_in[0];
    const float* log_A_real = (const float*)d_in[1];
    const float* A_imag     = (const float*)d_in[2];
    const float* Bmat       = (const float*)d_in[3];
    const float* Cmat       = (const float*)d_in[4];
    float* out = (float*)d_out;

    dim3 grid(HH * CHUNKS_PER_H / WPB);   // 256 blocks
    dim3 block(32 * WPB);                 // 128 threads
    s4_vandermonde_kernel<<<grid, block>>>(log_dt, log_A_real, A_imag,
                                           Bmat, Cmat, out);
}